// round 1
// baseline (speedup 1.0000x reference)
#include <cuda_runtime.h>

// Problem shapes (fixed per reference)
#define BATCH 4
#define SEQ   4096
#define DIM   1024
#define MM    (BATCH * SEQ)   // 16384 rows
#define KK    DIM             // 1024
#define NN    (4 * DIM)       // 4096 cols: [q | k | v | gate]

#define NCHUNK 32
#define CHUNK  (SEQ / NCHUNK) // 128

// Scratch: [m][e] with e<3072 = qkv, e>=3072 = gate preact. 256 MB static.
static __device__ float g_scr[(size_t)MM * NN];
// Per-chunk partial sums of k*v, later overwritten with exclusive prefixes.
static __device__ float g_part[BATCH * NCHUNK * DIM];

// ---------------------------------------------------------------------------
// Fused GEMM: C[m,e] = sum_k x[m,k] * W[e,k] + bias[e]
// W rows 0..3071 from W_qkv, 3072..4095 from W_gate.
// 128x128 tile, BK=16, 256 threads, 8x8 per-thread microtile.
// ---------------------------------------------------------------------------
#define BM 128
#define BN 128
#define BK 16
#define TM 8
#define TN 8

__global__ __launch_bounds__(256)
void fused_gemm_kernel(const float* __restrict__ A,
                       const float* __restrict__ Wqkv,
                       const float* __restrict__ bqkv,
                       const float* __restrict__ Wg,
                       const float* __restrict__ bg)
{
    __shared__ float As[BK][BM];
    __shared__ float Bs[BK][BN];

    const int tid   = threadIdx.x;
    const int bm    = blockIdx.y;
    const int bn    = blockIdx.x;
    const int eBase = bn * BN;

    const float* Wsrc;
    const float* biasSrc;
    if (eBase < 3 * DIM) {
        Wsrc    = Wqkv + (size_t)eBase * KK;
        biasSrc = bqkv + eBase;
    } else {
        Wsrc    = Wg + (size_t)(eBase - 3 * DIM) * KK;
        biasSrc = bg + (eBase - 3 * DIM);
    }

    const float* Ablk = A + (size_t)bm * BM * KK;

    // Warp/lane layout: 8 warps as 2(N) x 4(M); lanes as 8(N) x 4(M).
    const int warp    = tid >> 5;
    const int lane    = tid & 31;
    const int warpX   = warp & 1;
    const int warpY   = warp >> 1;
    const int tx      = lane & 7;
    const int ty      = lane >> 3;
    const int colBase = warpX * 64 + tx * 8;   // [0,128)
    const int rowBase = warpY * 32 + ty * 8;   // [0,128)

    float acc[TM][TN];
#pragma unroll
    for (int i = 0; i < TM; i++)
#pragma unroll
        for (int j = 0; j < TN; j++) acc[i][j] = 0.0f;

    for (int k0 = 0; k0 < KK; k0 += BK) {
        // Load A/B tiles (128x16 each) via float4, store transposed to smem.
#pragma unroll
        for (int r = 0; r < 2; r++) {
            int fi  = tid + r * 256;     // float4 index in [0,512)
            int row = fi >> 2;           // [0,128)
            int c4  = (fi & 3) << 2;     // {0,4,8,12}
            float4 va = *(const float4*)(Ablk + (size_t)row * KK + k0 + c4);
            As[c4 + 0][row] = va.x;
            As[c4 + 1][row] = va.y;
            As[c4 + 2][row] = va.z;
            As[c4 + 3][row] = va.w;
            float4 vb = *(const float4*)(Wsrc + (size_t)row * KK + k0 + c4);
            Bs[c4 + 0][row] = vb.x;
            Bs[c4 + 1][row] = vb.y;
            Bs[c4 + 2][row] = vb.z;
            Bs[c4 + 3][row] = vb.w;
        }
        __syncthreads();

#pragma unroll
        for (int k = 0; k < BK; k++) {
            float4 a0 = *(const float4*)&As[k][rowBase];
            float4 a1 = *(const float4*)&As[k][rowBase + 4];
            float4 b0 = *(const float4*)&Bs[k][colBase];
            float4 b1 = *(const float4*)&Bs[k][colBase + 4];
            float ra[TM] = {a0.x, a0.y, a0.z, a0.w, a1.x, a1.y, a1.z, a1.w};
            float rb[TN] = {b0.x, b0.y, b0.z, b0.w, b1.x, b1.y, b1.z, b1.w};
#pragma unroll
            for (int i = 0; i < TM; i++)
#pragma unroll
                for (int j = 0; j < TN; j++)
                    acc[i][j] += ra[i] * rb[j];
        }
        __syncthreads();
    }

    // Epilogue: add bias, store to scratch.
    float bias[TN];
#pragma unroll
    for (int j = 0; j < TN; j++) bias[j] = biasSrc[colBase + j];

#pragma unroll
    for (int i = 0; i < TM; i++) {
        size_t m   = (size_t)(bm * BM + rowBase + i);
        float* dst = g_scr + m * NN + eBase + colBase;
        float4 o0  = make_float4(acc[i][0] + bias[0], acc[i][1] + bias[1],
                                 acc[i][2] + bias[2], acc[i][3] + bias[3]);
        float4 o1  = make_float4(acc[i][4] + bias[4], acc[i][5] + bias[5],
                                 acc[i][6] + bias[6], acc[i][7] + bias[7]);
        *(float4*)dst       = o0;
        *(float4*)(dst + 4) = o1;
    }
}

// ---------------------------------------------------------------------------
// Phase 2: per-chunk partial sums of k*v along s.
// Grid: (DIM/256, NCHUNK, BATCH); coalesced over d.
// ---------------------------------------------------------------------------
__global__ __launch_bounds__(256)
void chunk_sum_kernel()
{
    const int d = blockIdx.x * 256 + threadIdx.x;
    const int c = blockIdx.y;
    const int b = blockIdx.z;
    const float* base = g_scr + (size_t)(b * SEQ + c * CHUNK) * NN;
    float s = 0.0f;
#pragma unroll 4
    for (int i = 0; i < CHUNK; i++) {
        const float* row = base + (size_t)i * NN;
        s += row[DIM + d] * row[2 * DIM + d];
    }
    g_part[(b * NCHUNK + c) * DIM + d] = s;
}

// ---------------------------------------------------------------------------
// Phase 3: exclusive scan over the 32 chunk sums for each (b,d).
// ---------------------------------------------------------------------------
__global__ __launch_bounds__(256)
void scan_part_kernel()
{
    const int idx = blockIdx.x * 256 + threadIdx.x;  // [0, BATCH*DIM)
    const int b = idx / DIM;
    const int d = idx % DIM;
    float ex = 0.0f;
#pragma unroll
    for (int c = 0; c < NCHUNK; c++) {
        float t = g_part[(b * NCHUNK + c) * DIM + d];
        g_part[(b * NCHUNK + c) * DIM + d] = ex;
        ex += t;
    }
}

// ---------------------------------------------------------------------------
// Phase 4: within-chunk running sum + fused output q * state * sigmoid(gate).
// ---------------------------------------------------------------------------
__global__ __launch_bounds__(256)
void final_kernel(float* __restrict__ out)
{
    const int d = blockIdx.x * 256 + threadIdx.x;
    const int c = blockIdx.y;
    const int b = blockIdx.z;
    float acc = g_part[(b * NCHUNK + c) * DIM + d];
    const float* base  = g_scr + (size_t)(b * SEQ + c * CHUNK) * NN;
    float* obase       = out   + (size_t)(b * SEQ + c * CHUNK) * DIM;
#pragma unroll 4
    for (int i = 0; i < CHUNK; i++) {
        const float* row = base + (size_t)i * NN;
        acc += row[DIM + d] * row[2 * DIM + d];
        float qv = row[d];
        float gt = row[3 * DIM + d];
        float gv = 1.0f / (1.0f + __expf(-gt));
        obase[(size_t)i * DIM + d] = qv * acc * gv;
    }
}

// ---------------------------------------------------------------------------
extern "C" void kernel_launch(void* const* d_in, const int* in_sizes, int n_in,
                              void* d_out, int out_size)
{
    const float* x    = (const float*)d_in[0];
    const float* Wqkv = (const float*)d_in[1];
    const float* bqkv = (const float*)d_in[2];
    const float* Wg   = (const float*)d_in[3];
    const float* bg   = (const float*)d_in[4];
    float* out        = (float*)d_out;

    dim3 ggrid(NN / BN, MM / BM);   // (32, 128)
    fused_gemm_kernel<<<ggrid, 256>>>(x, Wqkv, bqkv, Wg, bg);

    dim3 cgrid(DIM / 256, NCHUNK, BATCH);
    chunk_sum_kernel<<<cgrid, 256>>>();
    scan_part_kernel<<<(BATCH * DIM) / 256, 256>>>();
    final_kernel<<<cgrid, 256>>>(out);
}

// round 4
// speedup vs baseline: 2.1382x; 2.1382x over previous
#include <cuda_runtime.h>
#include <cuda_bf16.h>
#include <cstdint>

// ---------------------------------------------------------------- shapes
#define BATCH 4
#define SEQ   4096
#define DIM   1024
#define MM    (BATCH * SEQ)   // 16384
#define KK    DIM             // 1024
#define NN    (4 * DIM)       // 4096 : [q | k | v | gate]

// GEMM tiling
#define BM 128
#define BN 128
#define BK 32
#define KITERS (KK / BK)      // 32
// scan chunking
#define NCHUNK_S 32
#define CHUNK_S  (SEQ / NCHUNK_S)  // 128

// ---------------------------------------------------------------- scratch
static __device__ __nv_bfloat16 g_Ahi[(size_t)MM * KK];
static __device__ __nv_bfloat16 g_Alo[(size_t)MM * KK];
static __device__ __nv_bfloat16 g_Whi[(size_t)NN * KK];
static __device__ __nv_bfloat16 g_Wlo[(size_t)NN * KK];
static __device__ float        g_ball[NN];
static __device__ float        g_scr[(size_t)MM * NN];    // 256 MB
static __device__ float        g_part[BATCH * NCHUNK_S * DIM];

// ---------------------------------------------------------------- helpers
__device__ __forceinline__ uint32_t smem_u32(const void* p) {
    uint32_t a;
    asm("{ .reg .u64 t; cvta.to.shared.u64 t, %1; cvt.u32.u64 %0, t; }" : "=r"(a) : "l"(p));
    return a;
}

__device__ __forceinline__ void cp_async16(uint32_t smem_addr, const void* gptr) {
    asm volatile("cp.async.cg.shared.global [%0], [%1], 16;"
                 :: "r"(smem_addr), "l"(gptr) : "memory");
}
#define CP_COMMIT() asm volatile("cp.async.commit_group;" ::: "memory")
#define CP_WAIT1()  asm volatile("cp.async.wait_group 1;" ::: "memory")
#define CP_WAIT0()  asm volatile("cp.async.wait_group 0;" ::: "memory")

__device__ __forceinline__ void ldm_x4(uint32_t* r, uint32_t addr) {
    asm volatile("ldmatrix.sync.aligned.m8n8.x4.shared.b16 {%0,%1,%2,%3}, [%4];"
                 : "=r"(r[0]), "=r"(r[1]), "=r"(r[2]), "=r"(r[3]) : "r"(addr));
}

__device__ __forceinline__ void mma16816(float* c, const uint32_t* a, const uint32_t* b) {
    asm volatile(
        "mma.sync.aligned.m16n8k16.row.col.f32.bf16.bf16.f32 "
        "{%0,%1,%2,%3}, {%4,%5,%6,%7}, {%8,%9}, {%0,%1,%2,%3};"
        : "+f"(c[0]), "+f"(c[1]), "+f"(c[2]), "+f"(c[3])
        : "r"(a[0]), "r"(a[1]), "r"(a[2]), "r"(a[3]), "r"(b[0]), "r"(b[1]));
}

// ---------------------------------------------------------------- conversion
__device__ __forceinline__ void split_hl(float x, __nv_bfloat16& h, __nv_bfloat16& l) {
    h = __float2bfloat16_rn(x);
    l = __float2bfloat16_rn(x - __bfloat162float(h));
}

__global__ __launch_bounds__(256)
void conv_x_kernel(const float* __restrict__ x)
{
    size_t i = (size_t)blockIdx.x * 256 + threadIdx.x;   // float4 index
    float4 v = ((const float4*)x)[i];
    size_t o = i * 4;
    float a[4] = {v.x, v.y, v.z, v.w};
#pragma unroll
    for (int j = 0; j < 4; j++) {
        __nv_bfloat16 h, l;
        split_hl(a[j], h, l);
        g_Ahi[o + j] = h;
        g_Alo[o + j] = l;
    }
}

__global__ __launch_bounds__(256)
void conv_w_kernel(const float* __restrict__ Wqkv, const float* __restrict__ bqkv,
                   const float* __restrict__ Wg,   const float* __restrict__ bg)
{
    int e = blockIdx.x;                  // [0, NN)
    int t = threadIdx.x;                 // 256 threads -> KK/4 = 256 float4 per row
    const float* src = (e < 3 * DIM) ? (Wqkv + (size_t)e * KK)
                                     : (Wg + (size_t)(e - 3 * DIM) * KK);
    float4 v = ((const float4*)src)[t];
    size_t o = (size_t)e * KK + t * 4;
    float a[4] = {v.x, v.y, v.z, v.w};
#pragma unroll
    for (int j = 0; j < 4; j++) {
        __nv_bfloat16 h, l;
        split_hl(a[j], h, l);
        g_Whi[o + j] = h;
        g_Wlo[o + j] = l;
    }
    if (t == 0)
        g_ball[e] = (e < 3 * DIM) ? bqkv[e] : bg[e - 3 * DIM];
}

// ---------------------------------------------------------------- GEMM
// SMEM: padded tiles [128][40] bf16 (80-byte row stride -> conflict-light
// ldmatrix). Per stage: Ahi | Alo | Bhi | Blo, 10240 B each = 40960 B.
#define TPAD 40
#define TILE_B (128 * TPAD * 2)          // 10240
#define OFF_AHI 0
#define OFF_ALO (1 * TILE_B)
#define OFF_BHI (2 * TILE_B)
#define OFF_BLO (3 * TILE_B)
#define STAGE_B (4 * TILE_B)             // 40960
#define GEMM_SMEM (2 * STAGE_B)          // 81920

// Load one 128x32 bf16 tile stage: 512 x 16B chunks, 2 per thread per tile.
__device__ __forceinline__ void load_tile(uint32_t s_dst, const __nv_bfloat16* g_src,
                                          int k0, int tid)
{
#pragma unroll
    for (int it = 0; it < 2; it++) {
        int c   = tid + it * 256;        // [0,512)
        int row = c >> 2;
        int kc  = c & 3;                 // 16B chunk within the 64B row
        cp_async16(s_dst + (uint32_t)(row * (TPAD * 2) + kc * 16),
                   (const char*)(g_src + (size_t)row * KK + k0) + kc * 16);
    }
}

__global__ __launch_bounds__(256)
void gemm_hmma_kernel()
{
    extern __shared__ char smem[];
    const uint32_t sb = smem_u32(smem);
    const int tid  = threadIdx.x;
    const int wid  = tid >> 5;
    const int lane = tid & 31;
    const int bm   = blockIdx.y;
    const int bn   = blockIdx.x;
    const int wM   = wid >> 2;           // 0..1  (M warp)
    const int wN   = wid & 3;            // 0..3  (N warp)

    const __nv_bfloat16* Ahi = g_Ahi + (size_t)bm * BM * KK;
    const __nv_bfloat16* Alo = g_Alo + (size_t)bm * BM * KK;
    const __nv_bfloat16* Bhi = g_Whi + (size_t)bn * BN * KK;
    const __nv_bfloat16* Blo = g_Wlo + (size_t)bn * BN * KK;

    float acc[4][4][4];
#pragma unroll
    for (int i = 0; i < 4; i++)
#pragma unroll
        for (int j = 0; j < 4; j++)
#pragma unroll
            for (int r = 0; r < 4; r++) acc[i][j][r] = 0.0f;

    // ldmatrix base offsets within a tile
    // A (row-major m x k): lanes 0-15 -> rows m0-15 @ k0; lanes 16-31 -> m0-15 @ k8.
    const int aRow = wM * 64 + (lane & 15);
    const int aCol = (lane >> 4) * 8;
    // B ([n][k] row-major, NON-trans ldmatrix):
    //   lanes 0-7 -> n0-7 @ k0, 8-15 -> n0-7 @ k8, 16-23 -> n8-15 @ k0, 24-31 -> n8-15 @ k8
    //   => r0,r1 = mma B-frag (k0-7, k8-15) for n0-7; r2,r3 for n8-15.
    const int bRowN = wN * 32 + ((lane >> 4) * 8) + (lane & 7);
    const int bColK = ((lane >> 3) & 1) * 8;

    // ---- prologue: stage 0
    load_tile(sb + OFF_AHI, Ahi, 0, tid);
    load_tile(sb + OFF_ALO, Alo, 0, tid);
    load_tile(sb + OFF_BHI, Bhi, 0, tid);
    load_tile(sb + OFF_BLO, Blo, 0, tid);
    CP_COMMIT();

    for (int i = 0; i < KITERS; i++) {
        const uint32_t cur = sb + (uint32_t)(i & 1) * STAGE_B;
        if (i + 1 < KITERS) {
            const uint32_t nxt = sb + (uint32_t)((i + 1) & 1) * STAGE_B;
            const int k0 = (i + 1) * BK;
            load_tile(nxt + OFF_AHI, Ahi, k0, tid);
            load_tile(nxt + OFF_ALO, Alo, k0, tid);
            load_tile(nxt + OFF_BHI, Bhi, k0, tid);
            load_tile(nxt + OFF_BLO, Blo, k0, tid);
            CP_COMMIT();
            CP_WAIT1();
        } else {
            CP_WAIT0();
        }
        __syncthreads();

#pragma unroll
        for (int ks = 0; ks < 2; ks++) {
            uint32_t ahi[4][4], alo[4][4], bhi[4][2], blo[4][2];
#pragma unroll
            for (int nh = 0; nh < 2; nh++) {
                uint32_t r[4];
                uint32_t boff = (uint32_t)((bRowN + nh * 16) * (TPAD * 2) +
                                           (ks * 16 + bColK) * 2);
                ldm_x4(r, cur + OFF_BHI + boff);
                bhi[nh * 2 + 0][0] = r[0]; bhi[nh * 2 + 0][1] = r[1];
                bhi[nh * 2 + 1][0] = r[2]; bhi[nh * 2 + 1][1] = r[3];
                ldm_x4(r, cur + OFF_BLO + boff);
                blo[nh * 2 + 0][0] = r[0]; blo[nh * 2 + 0][1] = r[1];
                blo[nh * 2 + 1][0] = r[2]; blo[nh * 2 + 1][1] = r[3];
            }
#pragma unroll
            for (int mi = 0; mi < 4; mi++) {
                uint32_t aoff = (uint32_t)((aRow + mi * 16) * (TPAD * 2) +
                                           (ks * 16 + aCol) * 2);
                ldm_x4(ahi[mi], cur + OFF_AHI + aoff);
                ldm_x4(alo[mi], cur + OFF_ALO + aoff);
            }
            // pass 1: Ahi * Bhi
#pragma unroll
            for (int mi = 0; mi < 4; mi++)
#pragma unroll
                for (int ni = 0; ni < 4; ni++)
                    mma16816(acc[mi][ni], ahi[mi], bhi[ni]);
            // pass 2: Alo * Bhi
#pragma unroll
            for (int mi = 0; mi < 4; mi++)
#pragma unroll
                for (int ni = 0; ni < 4; ni++)
                    mma16816(acc[mi][ni], alo[mi], bhi[ni]);
            // pass 3: Ahi * Blo
#pragma unroll
            for (int mi = 0; mi < 4; mi++)
#pragma unroll
                for (int ni = 0; ni < 4; ni++)
                    mma16816(acc[mi][ni], ahi[mi], blo[ni]);
        }
        __syncthreads();
    }

    // ---- epilogue: C[16x8] frag: rows lane>>2 (+0/+8), cols (lane&3)*2 (+0/+1)
    const int g   = lane >> 2;
    const int tig = lane & 3;
    const int eBase = bn * BN;
#pragma unroll
    for (int mi = 0; mi < 4; mi++) {
#pragma unroll
        for (int ni = 0; ni < 4; ni++) {
            int col = eBase + wN * 32 + ni * 8 + tig * 2;
            float b0 = g_ball[col], b1 = g_ball[col + 1];
            size_t r0 = (size_t)(bm * BM + wM * 64 + mi * 16 + g);
            size_t r1 = r0 + 8;
            float2 v0 = make_float2(acc[mi][ni][0] + b0, acc[mi][ni][1] + b1);
            float2 v1 = make_float2(acc[mi][ni][2] + b0, acc[mi][ni][3] + b1);
            *(float2*)(g_scr + r0 * NN + col) = v0;
            *(float2*)(g_scr + r1 * NN + col) = v1;
        }
    }
}

// ---------------------------------------------------------------- scan phases
__global__ __launch_bounds__(256)
void chunk_sum_kernel()
{
    const int d = blockIdx.x * 256 + threadIdx.x;
    const int c = blockIdx.y;
    const int b = blockIdx.z;
    const float* base = g_scr + (size_t)(b * SEQ + c * CHUNK_S) * NN;
    float s = 0.0f;
#pragma unroll 4
    for (int i = 0; i < CHUNK_S; i++) {
        const float* row = base + (size_t)i * NN;
        s += row[DIM + d] * row[2 * DIM + d];
    }
    g_part[(b * NCHUNK_S + c) * DIM + d] = s;
}

__global__ __launch_bounds__(256)
void scan_part_kernel()
{
    const int idx = blockIdx.x * 256 + threadIdx.x;
    const int b = idx / DIM;
    const int d = idx % DIM;
    float ex = 0.0f;
#pragma unroll
    for (int c = 0; c < NCHUNK_S; c++) {
        float t = g_part[(b * NCHUNK_S + c) * DIM + d];
        g_part[(b * NCHUNK_S + c) * DIM + d] = ex;
        ex += t;
    }
}

__global__ __launch_bounds__(256)
void final_kernel(float* __restrict__ out)
{
    const int d = blockIdx.x * 256 + threadIdx.x;
    const int c = blockIdx.y;
    const int b = blockIdx.z;
    float acc = g_part[(b * NCHUNK_S + c) * DIM + d];
    const float* base = g_scr + (size_t)(b * SEQ + c * CHUNK_S) * NN;
    float* obase      = out   + (size_t)(b * SEQ + c * CHUNK_S) * DIM;
#pragma unroll 4
    for (int i = 0; i < CHUNK_S; i++) {
        const float* row = base + (size_t)i * NN;
        acc += row[DIM + d] * row[2 * DIM + d];
        float qv = row[d];
        float gt = row[3 * DIM + d];
        float gv = 1.0f / (1.0f + __expf(-gt));
        obase[(size_t)i * DIM + d] = qv * acc * gv;
    }
}

// ---------------------------------------------------------------- launch
extern "C" void kernel_launch(void* const* d_in, const int* in_sizes, int n_in,
                              void* d_out, int out_size)
{
    const float* x    = (const float*)d_in[0];
    const float* Wqkv = (const float*)d_in[1];
    const float* bqkv = (const float*)d_in[2];
    const float* Wg   = (const float*)d_in[3];
    const float* bg   = (const float*)d_in[4];
    float* out        = (float*)d_out;

    conv_x_kernel<<<(MM * KK / 4) / 256, 256>>>(x);
    conv_w_kernel<<<NN, 256>>>(Wqkv, bqkv, Wg, bg);

    cudaFuncSetAttribute(gemm_hmma_kernel,
                         cudaFuncAttributeMaxDynamicSharedMemorySize, GEMM_SMEM);
    dim3 ggrid(NN / BN, MM / BM);          // (32, 128)
    gemm_hmma_kernel<<<ggrid, 256, GEMM_SMEM>>>();

    dim3 cgrid(DIM / 256, NCHUNK_S, BATCH);
    chunk_sum_kernel<<<cgrid, 256>>>();
    scan_part_kernel<<<(BATCH * DIM) / 256, 256>>>();
    final_kernel<<<cgrid, 256>>>(out);
}

// round 5
// speedup vs baseline: 3.5257x; 1.6489x over previous
#include <cuda_runtime.h>
#include <cuda_fp16.h>
#include <cstdint>

// ---------------------------------------------------------------- shapes
#define BATCH 4
#define SEQ   4096
#define DIM   1024
#define MM    (BATCH * SEQ)   // 16384
#define KK    DIM             // 1024
#define NN    (4 * DIM)       // 4096 : [q | k | v | gate]

// GEMM tiling
#define BM 128
#define BN 128
#define BK 32
#define KITERS (KK / BK)      // 32
// scan chunking
#define NCHUNK_S 64
#define CHUNK_S  (SEQ / NCHUNK_S)  // 64

// ---------------------------------------------------------------- scratch
static __device__ __half g_Ahi[(size_t)MM * KK];
static __device__ __half g_Alo[(size_t)MM * KK];
static __device__ __half g_Wh [(size_t)NN * KK];
static __device__ float  g_ball[NN];
static __device__ float  g_scr[(size_t)MM * NN];    // 256 MB
static __device__ float  g_part[BATCH * NCHUNK_S * DIM];

// ---------------------------------------------------------------- helpers
__device__ __forceinline__ uint32_t smem_u32(const void* p) {
    uint32_t a;
    asm("{ .reg .u64 t; cvta.to.shared.u64 t, %1; cvt.u32.u64 %0, t; }" : "=r"(a) : "l"(p));
    return a;
}

__device__ __forceinline__ void cp_async16(uint32_t smem_addr, const void* gptr) {
    asm volatile("cp.async.cg.shared.global [%0], [%1], 16;"
                 :: "r"(smem_addr), "l"(gptr) : "memory");
}
#define CP_COMMIT() asm volatile("cp.async.commit_group;" ::: "memory")
#define CP_WAIT1()  asm volatile("cp.async.wait_group 1;" ::: "memory")
#define CP_WAIT0()  asm volatile("cp.async.wait_group 0;" ::: "memory")

__device__ __forceinline__ void ldm_x4(uint32_t* r, uint32_t addr) {
    asm volatile("ldmatrix.sync.aligned.m8n8.x4.shared.b16 {%0,%1,%2,%3}, [%4];"
                 : "=r"(r[0]), "=r"(r[1]), "=r"(r[2]), "=r"(r[3]) : "r"(addr));
}

__device__ __forceinline__ void mma16816(float* c, const uint32_t* a, const uint32_t* b) {
    asm volatile(
        "mma.sync.aligned.m16n8k16.row.col.f32.f16.f16.f32 "
        "{%0,%1,%2,%3}, {%4,%5,%6,%7}, {%8,%9}, {%0,%1,%2,%3};"
        : "+f"(c[0]), "+f"(c[1]), "+f"(c[2]), "+f"(c[3])
        : "r"(a[0]), "r"(a[1]), "r"(a[2]), "r"(a[3]), "r"(b[0]), "r"(b[1]));
}

// ---------------------------------------------------------------- conversion
__global__ __launch_bounds__(256)
void conv_x_kernel(const float* __restrict__ x)
{
    size_t i = (size_t)blockIdx.x * 256 + threadIdx.x;   // float4 index
    float4 v = ((const float4*)x)[i];
    size_t o = i * 4;
    float a[4] = {v.x, v.y, v.z, v.w};
#pragma unroll
    for (int j = 0; j < 4; j++) {
        __half h = __float2half_rn(a[j]);
        __half l = __float2half_rn(a[j] - __half2float(h));
        g_Ahi[o + j] = h;
        g_Alo[o + j] = l;
    }
}

__global__ __launch_bounds__(256)
void conv_w_kernel(const float* __restrict__ Wqkv, const float* __restrict__ bqkv,
                   const float* __restrict__ Wg,   const float* __restrict__ bg)
{
    int e = blockIdx.x;                  // [0, NN)
    int t = threadIdx.x;                 // 256 threads -> KK/4 = 256 float4 per row
    const float* src = (e < 3 * DIM) ? (Wqkv + (size_t)e * KK)
                                     : (Wg + (size_t)(e - 3 * DIM) * KK);
    float4 v = ((const float4*)src)[t];
    size_t o = (size_t)e * KK + t * 4;
    g_Wh[o + 0] = __float2half_rn(v.x);
    g_Wh[o + 1] = __float2half_rn(v.y);
    g_Wh[o + 2] = __float2half_rn(v.z);
    g_Wh[o + 3] = __float2half_rn(v.w);
    if (t == 0)
        g_ball[e] = (e < 3 * DIM) ? bqkv[e] : bg[e - 3 * DIM];
}

// ---------------------------------------------------------------- GEMM
// SMEM: padded tiles [128][40] fp16 (80-byte row stride -> conflict-free
// ldmatrix). Per stage: Ahi | Alo | B = 3 tiles x 10240 B = 30720 B.
// 3 stages -> 92160 B dynamic SMEM.
#define TPAD 40
#define TILE_B (128 * TPAD * 2)          // 10240
#define OFF_AHI 0
#define OFF_ALO (1 * TILE_B)
#define OFF_B   (2 * TILE_B)
#define STAGE_B (3 * TILE_B)             // 30720
#define NSTAGE 3
#define GEMM_SMEM (NSTAGE * STAGE_B)     // 92160

// Load one 128x32 fp16 tile: 512 x 16B chunks, 2 per thread.
__device__ __forceinline__ void load_tile(uint32_t s_dst, const __half* g_src,
                                          int k0, int tid)
{
#pragma unroll
    for (int it = 0; it < 2; it++) {
        int c   = tid + it * 256;        // [0,512)
        int row = c >> 2;
        int kc  = c & 3;                 // 16B chunk within the 64B row
        cp_async16(s_dst + (uint32_t)(row * (TPAD * 2) + kc * 16),
                   (const char*)(g_src + (size_t)row * KK + k0) + kc * 16);
    }
}

__global__ __launch_bounds__(256, 2)
void gemm_hmma_kernel()
{
    extern __shared__ char smem[];
    const uint32_t sb = smem_u32(smem);
    const int tid  = threadIdx.x;
    const int wid  = tid >> 5;
    const int lane = tid & 31;
    const int bm   = blockIdx.y;
    const int bn   = blockIdx.x;
    const int wM   = wid >> 2;           // 0..1  (M warp)
    const int wN   = wid & 3;            // 0..3  (N warp)

    const __half* Ahi = g_Ahi + (size_t)bm * BM * KK;
    const __half* Alo = g_Alo + (size_t)bm * BM * KK;
    const __half* Bh  = g_Wh  + (size_t)bn * BN * KK;

    float acc[4][4][4];
#pragma unroll
    for (int i = 0; i < 4; i++)
#pragma unroll
        for (int j = 0; j < 4; j++)
#pragma unroll
            for (int r = 0; r < 4; r++) acc[i][j][r] = 0.0f;

    // ldmatrix lane addressing (verified in R4):
    // A row-major m x k: lanes 0-15 -> m0-15 @ k0; 16-31 -> m0-15 @ k8.
    const int aRow = wM * 64 + (lane & 15);
    const int aCol = (lane >> 4) * 8;
    // B [n][k] row-major, NON-trans:
    //   0-7 -> n0-7@k0, 8-15 -> n0-7@k8, 16-23 -> n8-15@k0, 24-31 -> n8-15@k8
    const int bRowN = wN * 32 + ((lane >> 4) * 8) + (lane & 7);
    const int bColK = ((lane >> 3) & 1) * 8;

    // ---- prologue: stages 0,1
    load_tile(sb + 0 * STAGE_B + OFF_AHI, Ahi, 0, tid);
    load_tile(sb + 0 * STAGE_B + OFF_ALO, Alo, 0, tid);
    load_tile(sb + 0 * STAGE_B + OFF_B,   Bh,  0, tid);
    CP_COMMIT();
    load_tile(sb + 1 * STAGE_B + OFF_AHI, Ahi, BK, tid);
    load_tile(sb + 1 * STAGE_B + OFF_ALO, Alo, BK, tid);
    load_tile(sb + 1 * STAGE_B + OFF_B,   Bh,  BK, tid);
    CP_COMMIT();

    int slot = 0;       // slot of stage i
    int nslot = 2;      // slot where stage i+2 will be loaded
    for (int i = 0; i < KITERS; i++) {
        if (i < KITERS - 1) { CP_WAIT1(); } else { CP_WAIT0(); }
        __syncthreads();                         // stage i visible to all

        // prefetch stage i+2 (slot held stage i-1; all warps are past it)
        if (i + 2 < KITERS) {
            const uint32_t nb = sb + (uint32_t)nslot * STAGE_B;
            const int k0 = (i + 2) * BK;
            load_tile(nb + OFF_AHI, Ahi, k0, tid);
            load_tile(nb + OFF_ALO, Alo, k0, tid);
            load_tile(nb + OFF_B,   Bh,  k0, tid);
            CP_COMMIT();
        }

        const uint32_t cur = sb + (uint32_t)slot * STAGE_B;
#pragma unroll
        for (int ks = 0; ks < 2; ks++) {
            uint32_t ahi[4][4], alo[4][4], bf[4][2];
#pragma unroll
            for (int nh = 0; nh < 2; nh++) {
                uint32_t r[4];
                uint32_t boff = (uint32_t)((bRowN + nh * 16) * (TPAD * 2) +
                                           (ks * 16 + bColK) * 2);
                ldm_x4(r, cur + OFF_B + boff);
                bf[nh * 2 + 0][0] = r[0]; bf[nh * 2 + 0][1] = r[1];
                bf[nh * 2 + 1][0] = r[2]; bf[nh * 2 + 1][1] = r[3];
            }
#pragma unroll
            for (int mi = 0; mi < 4; mi++) {
                uint32_t aoff = (uint32_t)((aRow + mi * 16) * (TPAD * 2) +
                                           (ks * 16 + aCol) * 2);
                ldm_x4(ahi[mi], cur + OFF_AHI + aoff);
                ldm_x4(alo[mi], cur + OFF_ALO + aoff);
            }
            // pass 1: Ahi * B
#pragma unroll
            for (int mi = 0; mi < 4; mi++)
#pragma unroll
                for (int ni = 0; ni < 4; ni++)
                    mma16816(acc[mi][ni], ahi[mi], bf[ni]);
            // pass 2: Alo * B
#pragma unroll
            for (int mi = 0; mi < 4; mi++)
#pragma unroll
                for (int ni = 0; ni < 4; ni++)
                    mma16816(acc[mi][ni], alo[mi], bf[ni]);
        }
        slot  = (slot == NSTAGE - 1) ? 0 : slot + 1;
        nslot = (nslot == NSTAGE - 1) ? 0 : nslot + 1;
    }

    // ---- epilogue: C frag: rows lane>>2 (+0/+8), cols (lane&3)*2 (+0/+1)
    const int g   = lane >> 2;
    const int tig = lane & 3;
    const int eBase = bn * BN;
#pragma unroll
    for (int mi = 0; mi < 4; mi++) {
#pragma unroll
        for (int ni = 0; ni < 4; ni++) {
            int col = eBase + wN * 32 + ni * 8 + tig * 2;
            float b0 = g_ball[col], b1 = g_ball[col + 1];
            size_t r0 = (size_t)(bm * BM + wM * 64 + mi * 16 + g);
            size_t r1 = r0 + 8;
            float2 v0 = make_float2(acc[mi][ni][0] + b0, acc[mi][ni][1] + b1);
            float2 v1 = make_float2(acc[mi][ni][2] + b0, acc[mi][ni][3] + b1);
            *(float2*)(g_scr + r0 * NN + col) = v0;
            *(float2*)(g_scr + r1 * NN + col) = v1;
        }
    }
}

// ---------------------------------------------------------------- scan phases
__global__ __launch_bounds__(256)
void chunk_sum_kernel()
{
    const int d = blockIdx.x * 256 + threadIdx.x;
    const int c = blockIdx.y;
    const int b = blockIdx.z;
    const float* base = g_scr + (size_t)(b * SEQ + c * CHUNK_S) * NN;
    float s = 0.0f;
#pragma unroll 4
    for (int i = 0; i < CHUNK_S; i++) {
        const float* row = base + (size_t)i * NN;
        s += row[DIM + d] * row[2 * DIM + d];
    }
    g_part[(b * NCHUNK_S + c) * DIM + d] = s;
}

__global__ __launch_bounds__(256)
void scan_part_kernel()
{
    const int idx = blockIdx.x * 256 + threadIdx.x;
    const int b = idx / DIM;
    const int d = idx % DIM;
    float ex = 0.0f;
#pragma unroll
    for (int c = 0; c < NCHUNK_S; c++) {
        float t = g_part[(b * NCHUNK_S + c) * DIM + d];
        g_part[(b * NCHUNK_S + c) * DIM + d] = ex;
        ex += t;
    }
}

__global__ __launch_bounds__(256)
void final_kernel(float* __restrict__ out)
{
    const int d = blockIdx.x * 256 + threadIdx.x;
    const int c = blockIdx.y;
    const int b = blockIdx.z;
    float acc = g_part[(b * NCHUNK_S + c) * DIM + d];
    const float* base = g_scr + (size_t)(b * SEQ + c * CHUNK_S) * NN;
    float* obase      = out   + (size_t)(b * SEQ + c * CHUNK_S) * DIM;
#pragma unroll 4
    for (int i = 0; i < CHUNK_S; i++) {
        const float* row = base + (size_t)i * NN;
        acc += row[DIM + d] * row[2 * DIM + d];
        float qv = row[d];
        float gt = row[3 * DIM + d];
        float gv = 1.0f / (1.0f + __expf(-gt));
        obase[(size_t)i * DIM + d] = qv * acc * gv;
    }
}

// ---------------------------------------------------------------- launch
extern "C" void kernel_launch(void* const* d_in, const int* in_sizes, int n_in,
                              void* d_out, int out_size)
{
    const float* x    = (const float*)d_in[0];
    const float* Wqkv = (const float*)d_in[1];
    const float* bqkv = (const float*)d_in[2];
    const float* Wg   = (const float*)d_in[3];
    const float* bg   = (const float*)d_in[4];
    float* out        = (float*)d_out;

    conv_x_kernel<<<(MM * KK / 4) / 256, 256>>>(x);
    conv_w_kernel<<<NN, 256>>>(Wqkv, bqkv, Wg, bg);

    cudaFuncSetAttribute(gemm_hmma_kernel,
                         cudaFuncAttributeMaxDynamicSharedMemorySize, GEMM_SMEM);
    dim3 ggrid(NN / BN, MM / BM);          // (32, 128)
    gemm_hmma_kernel<<<ggrid, 256, GEMM_SMEM>>>();

    dim3 cgrid(DIM / 256, NCHUNK_S, BATCH);
    chunk_sum_kernel<<<cgrid, 256>>>();
    scan_part_kernel<<<(BATCH * DIM) / 256, 256>>>();
    final_kernel<<<cgrid, 256>>>(out);
}

// round 6
// speedup vs baseline: 3.6264x; 1.0286x over previous
#include <cuda_runtime.h>
#include <cuda_fp16.h>
#include <cstdint>

// ---------------------------------------------------------------- shapes
#define BATCH 4
#define SEQ   4096
#define DIM   1024
#define MM    (BATCH * SEQ)   // 16384
#define KK    DIM             // 1024
#define NN    (4 * DIM)       // 4096 : interleaved [q k v g] per dim

// GEMM tiling
#define BM 128
#define BN 128
#define BK 32
#define KITERS (KK / BK)      // 32
// scan chunking: one GEMM M-block == one chunk
#define NCHUNK_S 32
#define CHUNK_S  128

// ---------------------------------------------------------------- scratch
static __device__ __half g_Ahi[(size_t)MM * KK];
static __device__ __half g_Alo[(size_t)MM * KK];
static __device__ __half g_Wh [(size_t)NN * KK];    // column-permuted: e' = 4d+j
static __device__ float  g_ball[NN];                 // permuted bias
static __device__ float  g_q [(size_t)MM * DIM];
static __device__ float  g_kv[(size_t)MM * DIM];
static __device__ float  g_gs[(size_t)MM * DIM];
static __device__ float  g_part[BATCH * NCHUNK_S * DIM];

// ---------------------------------------------------------------- helpers
__device__ __forceinline__ uint32_t smem_u32(const void* p) {
    uint32_t a;
    asm("{ .reg .u64 t; cvta.to.shared.u64 t, %1; cvt.u32.u64 %0, t; }" : "=r"(a) : "l"(p));
    return a;
}

__device__ __forceinline__ void cp_async16(uint32_t smem_addr, const void* gptr) {
    asm volatile("cp.async.cg.shared.global [%0], [%1], 16;"
                 :: "r"(smem_addr), "l"(gptr) : "memory");
}
#define CP_COMMIT() asm volatile("cp.async.commit_group;" ::: "memory")
#define CP_WAIT1()  asm volatile("cp.async.wait_group 1;" ::: "memory")
#define CP_WAIT0()  asm volatile("cp.async.wait_group 0;" ::: "memory")

__device__ __forceinline__ void ldm_x4(uint32_t* r, uint32_t addr) {
    asm volatile("ldmatrix.sync.aligned.m8n8.x4.shared.b16 {%0,%1,%2,%3}, [%4];"
                 : "=r"(r[0]), "=r"(r[1]), "=r"(r[2]), "=r"(r[3]) : "r"(addr));
}

__device__ __forceinline__ void mma16816(float* c, const uint32_t* a, const uint32_t* b) {
    asm volatile(
        "mma.sync.aligned.m16n8k16.row.col.f32.f16.f16.f32 "
        "{%0,%1,%2,%3}, {%4,%5,%6,%7}, {%8,%9}, {%0,%1,%2,%3};"
        : "+f"(c[0]), "+f"(c[1]), "+f"(c[2]), "+f"(c[3])
        : "r"(a[0]), "r"(a[1]), "r"(a[2]), "r"(a[3]), "r"(b[0]), "r"(b[1]));
}

// ---------------------------------------------------------------- conversion
__global__ __launch_bounds__(256)
void conv_x_kernel(const float* __restrict__ x)
{
    size_t i = (size_t)blockIdx.x * 256 + threadIdx.x;   // float4 index
    float4 v = ((const float4*)x)[i];
    size_t o = i * 4;
    float a[4] = {v.x, v.y, v.z, v.w};
#pragma unroll
    for (int j = 0; j < 4; j++) {
        __half h = __float2half_rn(a[j]);
        __half l = __float2half_rn(a[j] - __half2float(h));
        g_Ahi[o + j] = h;
        g_Alo[o + j] = l;
    }
}

// Permuted W: destination column e' = 4d + j, j in {0:q, 1:k, 2:v, 3:gate}.
__global__ __launch_bounds__(256)
void conv_w_kernel(const float* __restrict__ Wqkv, const float* __restrict__ bqkv,
                   const float* __restrict__ Wg,   const float* __restrict__ bg)
{
    int ep = blockIdx.x;                 // [0, NN) permuted col
    int d  = ep >> 2;
    int j  = ep & 3;
    int t  = threadIdx.x;                // 256 threads -> KK/4 float4 per row
    const float* src = (j < 3) ? (Wqkv + (size_t)(j * DIM + d) * KK)
                               : (Wg + (size_t)d * KK);
    float4 v = ((const float4*)src)[t];
    size_t o = (size_t)ep * KK + t * 4;
    g_Wh[o + 0] = __float2half_rn(v.x);
    g_Wh[o + 1] = __float2half_rn(v.y);
    g_Wh[o + 2] = __float2half_rn(v.z);
    g_Wh[o + 3] = __float2half_rn(v.w);
    if (t == 0)
        g_ball[ep] = (j < 3) ? bqkv[j * DIM + d] : bg[d];
}

// ---------------------------------------------------------------- GEMM
// SMEM: padded tiles [128][40] fp16. Per stage: Ahi | Alo | B = 30720 B.
// 3 stages = 92160 B; epilogue reuses bytes [0,64K) as C tile + [64K,65K) red.
#define TPAD 40
#define TILE_B (128 * TPAD * 2)          // 10240
#define OFF_AHI 0
#define OFF_ALO (1 * TILE_B)
#define OFF_B   (2 * TILE_B)
#define STAGE_B (3 * TILE_B)             // 30720
#define NSTAGE 3
#define GEMM_SMEM (NSTAGE * STAGE_B)     // 92160

__device__ __forceinline__ void load_tile(uint32_t s_dst, const __half* g_src,
                                          int k0, int tid)
{
#pragma unroll
    for (int it = 0; it < 2; it++) {
        int c   = tid + it * 256;        // [0,512)
        int row = c >> 2;
        int kc  = c & 3;
        cp_async16(s_dst + (uint32_t)(row * (TPAD * 2) + kc * 16),
                   (const char*)(g_src + (size_t)row * KK + k0) + kc * 16);
    }
}

__global__ __launch_bounds__(256, 2)
void gemm_hmma_kernel()
{
    extern __shared__ char smem[];
    const uint32_t sb = smem_u32(smem);
    const int tid  = threadIdx.x;
    const int wid  = tid >> 5;
    const int lane = tid & 31;
    const int bm   = blockIdx.y;
    const int bn   = blockIdx.x;
    const int wM   = wid >> 2;           // 0..1
    const int wN   = wid & 3;            // 0..3

    const __half* Ahi = g_Ahi + (size_t)bm * BM * KK;
    const __half* Alo = g_Alo + (size_t)bm * BM * KK;
    const __half* Bh  = g_Wh  + (size_t)bn * BN * KK;

    float acc[4][4][4];
#pragma unroll
    for (int i = 0; i < 4; i++)
#pragma unroll
        for (int j = 0; j < 4; j++)
#pragma unroll
            for (int r = 0; r < 4; r++) acc[i][j][r] = 0.0f;

    const int aRow = wM * 64 + (lane & 15);
    const int aCol = (lane >> 4) * 8;
    const int bRowN = wN * 32 + ((lane >> 4) * 8) + (lane & 7);
    const int bColK = ((lane >> 3) & 1) * 8;

    // ---- prologue: stages 0,1
    load_tile(sb + 0 * STAGE_B + OFF_AHI, Ahi, 0, tid);
    load_tile(sb + 0 * STAGE_B + OFF_ALO, Alo, 0, tid);
    load_tile(sb + 0 * STAGE_B + OFF_B,   Bh,  0, tid);
    CP_COMMIT();
    load_tile(sb + 1 * STAGE_B + OFF_AHI, Ahi, BK, tid);
    load_tile(sb + 1 * STAGE_B + OFF_ALO, Alo, BK, tid);
    load_tile(sb + 1 * STAGE_B + OFF_B,   Bh,  BK, tid);
    CP_COMMIT();

    int slot = 0, nslot = 2;
    for (int i = 0; i < KITERS; i++) {
        if (i < KITERS - 1) { CP_WAIT1(); } else { CP_WAIT0(); }
        __syncthreads();

        if (i + 2 < KITERS) {
            const uint32_t nb = sb + (uint32_t)nslot * STAGE_B;
            const int k0 = (i + 2) * BK;
            load_tile(nb + OFF_AHI, Ahi, k0, tid);
            load_tile(nb + OFF_ALO, Alo, k0, tid);
            load_tile(nb + OFF_B,   Bh,  k0, tid);
            CP_COMMIT();
        }

        const uint32_t cur = sb + (uint32_t)slot * STAGE_B;
#pragma unroll
        for (int ks = 0; ks < 2; ks++) {
            uint32_t ahi[4][4], alo[4][4], bf[4][2];
#pragma unroll
            for (int nh = 0; nh < 2; nh++) {
                uint32_t r[4];
                uint32_t boff = (uint32_t)((bRowN + nh * 16) * (TPAD * 2) +
                                           (ks * 16 + bColK) * 2);
                ldm_x4(r, cur + OFF_B + boff);
                bf[nh * 2 + 0][0] = r[0]; bf[nh * 2 + 0][1] = r[1];
                bf[nh * 2 + 1][0] = r[2]; bf[nh * 2 + 1][1] = r[3];
            }
#pragma unroll
            for (int mi = 0; mi < 4; mi++) {
                uint32_t aoff = (uint32_t)((aRow + mi * 16) * (TPAD * 2) +
                                           (ks * 16 + aCol) * 2);
                ldm_x4(ahi[mi], cur + OFF_AHI + aoff);
                ldm_x4(alo[mi], cur + OFF_ALO + aoff);
            }
#pragma unroll
            for (int mi = 0; mi < 4; mi++)
#pragma unroll
                for (int ni = 0; ni < 4; ni++)
                    mma16816(acc[mi][ni], ahi[mi], bf[ni]);
#pragma unroll
            for (int mi = 0; mi < 4; mi++)
#pragma unroll
                for (int ni = 0; ni < 4; ni++)
                    mma16816(acc[mi][ni], alo[mi], bf[ni]);
        }
        slot  = (slot == NSTAGE - 1) ? 0 : slot + 1;
        nslot = (nslot == NSTAGE - 1) ? 0 : nslot + 1;
    }

    // ---- fused epilogue ------------------------------------------------
    // Stage C tile (128x128 fp32, 64 KB) through smem, then each thread
    // processes 16 rows of one local dim: q,k,v,g -> q, kv, sigmoid(g),
    // plus the per-chunk partial sum of kv.
    __syncthreads();                      // all ldmatrix reads done
    float* C = (float*)smem;
    const int g   = lane >> 2;
    const int tig = lane & 3;
#pragma unroll
    for (int mi = 0; mi < 4; mi++) {
#pragma unroll
        for (int ni = 0; ni < 4; ni++) {
            int col  = wN * 32 + ni * 8 + tig * 2;
            int row0 = wM * 64 + mi * 16 + g;
            C[row0 * 128 + col]       = acc[mi][ni][0];
            C[row0 * 128 + col + 1]   = acc[mi][ni][1];
            C[(row0 + 8) * 128 + col]     = acc[mi][ni][2];
            C[(row0 + 8) * 128 + col + 1] = acc[mi][ni][3];
        }
    }
    __syncthreads();

    const int dl = tid & 31;             // local dim 0..31
    const int rg = tid >> 5;             // row group 0..7 (16 rows each)
    const int dg = bn * 32 + dl;         // global dim
    const size_t m0 = (size_t)bm * BM;
    float4 bias = ((const float4*)g_ball)[bn * 32 + dl];
    float psum = 0.0f;
#pragma unroll 4
    for (int r = rg * 16; r < rg * 16 + 16; r++) {
        float4 c4 = ((const float4*)C)[r * 32 + dl];
        float qv = c4.x + bias.x;
        float kv = (c4.y + bias.y) * (c4.z + bias.z);
        float gt = c4.w + bias.w;
        float gs = 1.0f / (1.0f + __expf(-gt));
        size_t idx = (m0 + r) * DIM + dg;
        g_q [idx] = qv;
        g_kv[idx] = kv;
        g_gs[idx] = gs;
        psum += kv;
    }
    float* red = (float*)(smem + 65536);
    red[rg * 32 + dl] = psum;
    __syncthreads();
    if (tid < 32) {
        float s = 0.0f;
#pragma unroll
        for (int j = 0; j < 8; j++) s += red[j * 32 + tid];
        // bm -> batch b = bm/32, chunk c = bm%32
        g_part[bm * DIM + bn * 32 + tid] = s;   // (b*32+c)*DIM == bm*DIM
    }
}

// ---------------------------------------------------------------- scan phases
__global__ __launch_bounds__(256)
void scan_part_kernel()
{
    const int idx = blockIdx.x * 256 + threadIdx.x;
    const int b = idx / DIM;
    const int d = idx % DIM;
    float ex = 0.0f;
#pragma unroll
    for (int c = 0; c < NCHUNK_S; c++) {
        float t = g_part[(b * NCHUNK_S + c) * DIM + d];
        g_part[(b * NCHUNK_S + c) * DIM + d] = ex;
        ex += t;
    }
}

__global__ __launch_bounds__(256)
void final_kernel(float* __restrict__ out)
{
    const int d = blockIdx.x * 256 + threadIdx.x;
    const int c = blockIdx.y;
    const int b = blockIdx.z;
    float acc = g_part[(b * NCHUNK_S + c) * DIM + d];
    const size_t m0 = (size_t)(b * SEQ + c * CHUNK_S);
#pragma unroll 4
    for (int i = 0; i < CHUNK_S; i++) {
        size_t idx = (m0 + i) * DIM + d;
        acc += g_kv[idx];
        out[idx] = g_q[idx] * acc * g_gs[idx];
    }
}

// ---------------------------------------------------------------- launch
extern "C" void kernel_launch(void* const* d_in, const int* in_sizes, int n_in,
                              void* d_out, int out_size)
{
    const float* x    = (const float*)d_in[0];
    const float* Wqkv = (const float*)d_in[1];
    const float* bqkv = (const float*)d_in[2];
    const float* Wg   = (const float*)d_in[3];
    const float* bg   = (const float*)d_in[4];
    float* out        = (float*)d_out;

    conv_x_kernel<<<(MM * KK / 4) / 256, 256>>>(x);
    conv_w_kernel<<<NN, 256>>>(Wqkv, bqkv, Wg, bg);

    cudaFuncSetAttribute(gemm_hmma_kernel,
                         cudaFuncAttributeMaxDynamicSharedMemorySize, GEMM_SMEM);
    dim3 ggrid(NN / BN, MM / BM);          // (32, 128)
    gemm_hmma_kernel<<<ggrid, 256, GEMM_SMEM>>>();

    scan_part_kernel<<<(BATCH * DIM) / 256, 256>>>();
    dim3 fgrid(DIM / 256, NCHUNK_S, BATCH);
    final_kernel<<<fgrid, 256>>>(out);
}